// round 2
// baseline (speedup 1.0000x reference)
#include <cuda_runtime.h>

#define N_ATOMS 131072
#define CH      256
#define D_DOM   16384
#define M_MSG   65536
#define E_EDGE  262144

// ---------------- scratch (device globals; no allocations allowed) ----------
__device__ float g_xa[(size_t)N_ATOMS * CH];   // x @ W0^T
__device__ float g_msg[(size_t)M_MSG * CH];    // segsum(x[src], ii)
__device__ float g_msgb[(size_t)M_MSG * CH];   // msg @ W1^T
__device__ float g_xinv[(size_t)D_DOM * CH];   // segmean(x, dom)
__device__ float g_u2[(size_t)D_DOM * CH];     // x_inv @ W2^T
__device__ float g_r1[(size_t)D_DOM * CH];     // segsum(msg, dme1)
__device__ float g_r2[(size_t)D_DOM * CH];     // segsum(x_inv[dme0], dme1)
__device__ float g_inv[(size_t)D_DOM * CH];    // inv_maps

// ---------------- helpers ---------------------------------------------------
__device__ __forceinline__ int lower_bound_dev(const int* __restrict__ a, int n, int v) {
    int lo = 0, hi = n;
    while (lo < hi) { int mid = (lo + hi) >> 1; if (a[mid] < v) lo = mid + 1; else hi = mid; }
    return lo;
}

__device__ __forceinline__ void red_add_v4(float* p, float4 v) {
    asm volatile("red.global.add.v4.f32 [%0], {%1,%2,%3,%4};"
                 :: "l"(p), "f"(v.x), "f"(v.y), "f"(v.z), "f"(v.w) : "memory");
}

// ---------------- segment mean over sorted domain_indicator -> g_xinv -------
__global__ void segmean_kernel(const float* __restrict__ x, const int* __restrict__ dom) {
    __shared__ int s_lo, s_hi;
    int d = blockIdx.x;
    if (threadIdx.x == 0) {
        s_lo = lower_bound_dev(dom, N_ATOMS, d);
        s_hi = lower_bound_dev(dom, N_ATOMS, d + 1);
    }
    __syncthreads();
    int lo = s_lo, hi = s_hi, c = threadIdx.x;
    float s = 0.f;
    for (int r = lo; r < hi; r++) s += x[(size_t)r * CH + c];
    int cnt = hi - lo;
    g_xinv[(size_t)d * CH + c] = s / (float)(cnt > 0 ? cnt : 1);
}

// ---------------- segment sum over sorted intersect_indicator -> g_msg ------
__global__ void segmsg_kernel(const float* __restrict__ x, const int* __restrict__ ii,
                              const int* __restrict__ src) {
    __shared__ int s_lo, s_hi;
    int m = blockIdx.x;
    if (threadIdx.x == 0) {
        s_lo = lower_bound_dev(ii, E_EDGE, m);
        s_hi = lower_bound_dev(ii, E_EDGE, m + 1);
    }
    __syncthreads();
    int lo = s_lo, hi = s_hi, c = threadIdx.x;
    float s = 0.f;
    for (int e = lo; e < hi; e++) s += x[(size_t)src[e] * CH + c];
    g_msg[(size_t)m * CH + c] = s;
}

// ---------------- zero r1/r2 -------------------------------------------------
__global__ void zero_kernel() {
    int i = blockIdx.x * blockDim.x + threadIdx.x;   // over D*CH/4 float4s
    float4 z = make_float4(0.f, 0.f, 0.f, 0.f);
    ((float4*)g_r1)[i] = z;
    ((float4*)g_r2)[i] = z;
}

// ---------------- message -> domain scatters (r1, r2) ------------------------
__global__ void dom_scatter_kernel(const int* __restrict__ dme) {
    int m = blockIdx.x * 4 + (threadIdx.x >> 6);
    int c = threadIdx.x & 63;
    int d0 = dme[m];
    int d1 = dme[M_MSG + m];
    float4 a = ((const float4*)g_msg)[(size_t)m * 64 + c];
    float4 b = ((const float4*)g_xinv)[(size_t)d0 * 64 + c];
    red_add_v4(&g_r1[((size_t)d1 * 64 + c) * 4], a);
    red_add_v4(&g_r2[((size_t)d1 * 64 + c) * 4], b);
}

// ---------------- fp32 tiled GEMM: C[i,j] (+)= sum_k A[i,k] * W[j,k] ---------
// K fixed = 256, 256 output cols, 64x64 tile, BK=16, 256 threads, 4x4 microtile
__global__ void gemm_k256_kernel(const float* __restrict__ A, const float* __restrict__ W,
                                 int ldw, float* __restrict__ Cm, int acc) {
    __shared__ float As[16][68];
    __shared__ float Bs[16][68];
    int tid = threadIdx.x;
    int row0 = blockIdx.x * 64, col0 = blockIdx.y * 64;
    int lr = tid >> 2;          // 0..63
    int lc = (tid & 3) * 4;     // 0,4,8,12
    int tx = tid & 15, ty = tid >> 4;
    float accv[4][4];
#pragma unroll
    for (int i = 0; i < 4; i++)
#pragma unroll
        for (int j = 0; j < 4; j++) accv[i][j] = 0.f;

    for (int k0 = 0; k0 < 256; k0 += 16) {
        float4 av = *(const float4*)(A + (size_t)(row0 + lr) * 256 + k0 + lc);
        float4 bv = *(const float4*)(W + (size_t)(col0 + lr) * ldw + k0 + lc);
        As[lc + 0][lr] = av.x; As[lc + 1][lr] = av.y; As[lc + 2][lr] = av.z; As[lc + 3][lr] = av.w;
        Bs[lc + 0][lr] = bv.x; Bs[lc + 1][lr] = bv.y; Bs[lc + 2][lr] = bv.z; Bs[lc + 3][lr] = bv.w;
        __syncthreads();
#pragma unroll
        for (int k = 0; k < 16; k++) {
            float4 a = *(const float4*)&As[k][ty * 4];
            float4 b = *(const float4*)&Bs[k][tx * 4];
            accv[0][0] += a.x * b.x; accv[0][1] += a.x * b.y; accv[0][2] += a.x * b.z; accv[0][3] += a.x * b.w;
            accv[1][0] += a.y * b.x; accv[1][1] += a.y * b.y; accv[1][2] += a.y * b.z; accv[1][3] += a.y * b.w;
            accv[2][0] += a.z * b.x; accv[2][1] += a.z * b.y; accv[2][2] += a.z * b.z; accv[2][3] += a.z * b.w;
            accv[3][0] += a.w * b.x; accv[3][1] += a.w * b.y; accv[3][2] += a.w * b.z; accv[3][3] += a.w * b.w;
        }
        __syncthreads();
    }
#pragma unroll
    for (int i = 0; i < 4; i++) {
        float* cp = Cm + (size_t)(row0 + ty * 4 + i) * 256 + col0 + tx * 4;
        float4 v = make_float4(accv[i][0], accv[i][1], accv[i][2], accv[i][3]);
        if (acc) {
            float4 o = *(const float4*)cp;
            v.x += o.x; v.y += o.y; v.z += o.z; v.w += o.w;
        }
        *(float4*)cp = v;
    }
}

// ---------------- per-edge scatter into out ----------------------------------
// out[tgt[e]] += xa[src[e]] + msgb[ii[e]] + u2[dme0[ii[e]]]
__global__ void edge_scatter_kernel(const int* __restrict__ nme, const int* __restrict__ ii,
                                    const int* __restrict__ dme, float* __restrict__ out) {
    int e = blockIdx.x * 4 + (threadIdx.x >> 6);
    int c = threadIdx.x & 63;
    int s = nme[e];
    int t = nme[E_EDGE + e];
    int m = ii[e];
    int d0 = dme[m];
    float4 a = ((const float4*)g_xa)[(size_t)s * 64 + c];
    float4 b = ((const float4*)g_msgb)[(size_t)m * 64 + c];
    float4 u = ((const float4*)g_u2)[(size_t)d0 * 64 + c];
    float4 v = make_float4(a.x + b.x + u.x, a.y + b.y + u.y, a.z + b.z + u.z, a.w + b.w + u.w);
    red_add_v4(out + (size_t)t * 256 + c * 4, v);
}

// ---------------- out[n] += inv_maps[dom[n]] ---------------------------------
__global__ void final_add_kernel(const int* __restrict__ dom, float* __restrict__ out) {
    int n = blockIdx.x * 4 + (threadIdx.x >> 6);
    int c = threadIdx.x & 63;
    int d = dom[n];
    float4 v = ((float4*)out)[(size_t)n * 64 + c];
    float4 iv = ((const float4*)g_inv)[(size_t)d * 64 + c];
    v.x += iv.x; v.y += iv.y; v.z += iv.z; v.w += iv.w;
    ((float4*)out)[(size_t)n * 64 + c] = v;
}

// ---------------- launch ------------------------------------------------------
extern "C" void kernel_launch(void* const* d_in, const int* in_sizes, int n_in,
                              void* d_out, int out_size) {
    const float* x        = (const float*)d_in[0];
    const int*   dom      = (const int*)d_in[1];
    const int*   nme      = (const int*)d_in[2];   // [2, E] : src then tgt
    const int*   ii       = (const int*)d_in[3];
    const int*   dme      = (const int*)d_in[4];   // [2, M] : dme0 then dme1
    const float* Wtf_int  = (const float*)d_in[5]; // [256, 768]
    const float* Wtf_inv  = (const float*)d_in[6]; // [256, 512]
    const float* Wlin_inv = (const float*)d_in[7]; // [256, 256]
    const float* Wlin_id  = (const float*)d_in[8]; // [256, 256]
    float* out = (float*)d_out;

    float *xa, *msg, *msgb, *xinv, *u2, *r1, *r2, *inv;
    cudaGetSymbolAddress((void**)&xa,   g_xa);
    cudaGetSymbolAddress((void**)&msg,  g_msg);
    cudaGetSymbolAddress((void**)&msgb, g_msgb);
    cudaGetSymbolAddress((void**)&xinv, g_xinv);
    cudaGetSymbolAddress((void**)&u2,   g_u2);
    cudaGetSymbolAddress((void**)&r1,   g_r1);
    cudaGetSymbolAddress((void**)&r2,   g_r2);
    cudaGetSymbolAddress((void**)&inv,  g_inv);

    // segment reductions (sorted indicators -> binary-searched ranges)
    segmean_kernel<<<D_DOM, 256>>>(x, dom);
    segmsg_kernel<<<M_MSG, 256>>>(x, ii, nme);

    // r1 = segsum(msg, dme1); r2 = segsum(x_inv[dme0], dme1)
    zero_kernel<<<(D_DOM * CH / 4) / 256, 256>>>();
    dom_scatter_kernel<<<M_MSG / 4, 256>>>(dme);

    // GEMMs (weights pushed to the smallest level each map can live at)
    gemm_k256_kernel<<<dim3(N_ATOMS / 64, 4), 256>>>(x,    Wlin_id,        256, out,  0);
    gemm_k256_kernel<<<dim3(N_ATOMS / 64, 4), 256>>>(x,    Wtf_int,        768, xa,   0);
    gemm_k256_kernel<<<dim3(M_MSG  / 64, 4), 256>>>(msg,  Wtf_int + 256,  768, msgb, 0);
    gemm_k256_kernel<<<dim3(D_DOM  / 64, 4), 256>>>(xinv, Wtf_int + 512,  768, u2,   0);
    gemm_k256_kernel<<<dim3(D_DOM  / 64, 4), 256>>>(xinv, Wlin_inv,       256, inv,  0);
    gemm_k256_kernel<<<dim3(D_DOM  / 64, 4), 256>>>(r1,   Wtf_inv,        512, inv,  1);
    gemm_k256_kernel<<<dim3(D_DOM  / 64, 4), 256>>>(r2,   Wtf_inv + 256,  512, inv,  1);

    // per-edge scatter of all three irreducible maps
    edge_scatter_kernel<<<E_EDGE / 4, 256>>>(nme, ii, dme, out);

    // add gathered invariant maps
    final_add_kernel<<<N_ATOMS / 4, 256>>>(dom, out);
}

// round 6
// speedup vs baseline: 2.0385x; 2.0385x over previous
#include <cuda_runtime.h>
#include <cstdint>

#define N_ATOMS 131072
#define CH      256
#define D_DOM   16384
#define M_MSG   65536
#define E_EDGE  262144

// ---------------- scratch (device globals; no allocations allowed) ----------
__device__ float g_xa[(size_t)N_ATOMS * CH];   // x @ W0^T
__device__ float g_msg[(size_t)M_MSG * CH];    // segsum(x[src], ii)
__device__ float g_msgb[(size_t)M_MSG * CH];   // msg @ W1^T
__device__ float g_xinv[(size_t)D_DOM * CH];   // segmean(x, dom)
__device__ float g_u2[(size_t)D_DOM * CH];     // x_inv @ W2^T
__device__ float g_r1[(size_t)D_DOM * CH];     // segsum(msg, dme1)
__device__ float g_r2[(size_t)D_DOM * CH];     // segsum(x_inv[dme0], dme1)
__device__ float g_inv[(size_t)D_DOM * CH];    // x_inv @ Wlin_inv^T
__device__ float g_inv2[(size_t)D_DOM * CH];   // r1@W4a^T + r2@W4b^T

// ---------------- helpers ----------------------------------------------------
__device__ __forceinline__ float to_tf32(float f) {
    float r; asm("cvt.rna.tf32.f32 %0, %1;" : "=f"(r) : "f"(f)); return r;
}
__device__ __forceinline__ void mma_tf32(float* c, const uint32_t* a, const uint32_t* b) {
    asm volatile("mma.sync.aligned.m16n8k8.row.col.f32.tf32.tf32.f32 "
                 "{%0,%1,%2,%3}, {%4,%5,%6,%7}, {%8,%9}, {%0,%1,%2,%3};"
                 : "+f"(c[0]), "+f"(c[1]), "+f"(c[2]), "+f"(c[3])
                 : "r"(a[0]), "r"(a[1]), "r"(a[2]), "r"(a[3]), "r"(b[0]), "r"(b[1]));
}
__device__ __forceinline__ int lower_bound_dev(const int* __restrict__ a, int n, int v) {
    int lo = 0, hi = n;
    while (lo < hi) { int mid = (lo + hi) >> 1; if (a[mid] < v) lo = mid + 1; else hi = mid; }
    return lo;
}
__device__ __forceinline__ void red_add_v4(float* p, float4 v) {
    asm volatile("red.global.add.v4.f32 [%0], {%1,%2,%3,%4};"
                 :: "l"(p), "f"(v.x), "f"(v.y), "f"(v.z), "f"(v.w) : "memory");
}

// ---------------- tf32 mma.sync GEMM -----------------------------------------
// C[i,j] = sum_k A1[i,k]*B1[j,k]  (+ sum_k A2[i,k]*B2[j,k] when A2 != null)
// A rows have leading dim 256 (K=256). Output C is [M, 256].
// CTA tile 128(M) x 256(N); 8 warps in 2x4 grid; warp tile 64x64 = 4x8 m16n8k8.
// K chunked at 32, double-buffered SMEM, pad to 36-float row stride.
#define ASTRIDE 36
#define ABUF (128 * ASTRIDE)          // floats per A buffer
#define BBUF (256 * ASTRIDE)          // floats per B buffer
#define SMEMSZ ((2 * ABUF + 2 * BBUF) * 4)

__global__ __launch_bounds__(256, 1)
void mma_gemm(const float* __restrict__ A1, const float* __restrict__ B1, int ldb1,
              const float* __restrict__ A2, const float* __restrict__ B2, int ldb2,
              float* __restrict__ C)
{
    extern __shared__ float sm[];
    float* Asm = sm;                    // [2][128][36]
    float* Bsm = sm + 2 * ABUF;         // [2][256][36]

    int tid = threadIdx.x, lane = tid & 31, wid = tid >> 5;
    int wm = (wid >> 2) * 64, wn = (wid & 3) * 64;
    int row0 = blockIdx.x * 128;
    int rr = tid >> 3, c4 = tid & 7;    // load mapping: 32 rows x 8 float4 per pass
    int nch = (A2 != nullptr) ? 16 : 8;

    float acc[4][8][4];
#pragma unroll
    for (int i = 0; i < 4; i++)
#pragma unroll
        for (int j = 0; j < 8; j++)
#pragma unroll
            for (int q = 0; q < 4; q++) acc[i][j][q] = 0.f;

    float4 ra[4], rb[8];

    auto issue_load = [&](int kc) {
        const float* A = (kc < 8) ? A1 : A2;
        const float* B = (kc < 8) ? B1 : B2;
        int ldb = (kc < 8) ? ldb1 : ldb2;
        int k0 = (kc & 7) * 32;
#pragma unroll
        for (int p = 0; p < 4; p++)
            ra[p] = *(const float4*)(A + (size_t)(row0 + p * 32 + rr) * 256 + k0 + c4 * 4);
#pragma unroll
        for (int p = 0; p < 8; p++)
            rb[p] = *(const float4*)(B + (size_t)(p * 32 + rr) * ldb + k0 + c4 * 4);
    };
    auto store_smem = [&](int buf) {
        float* a = Asm + buf * ABUF;
        float* b = Bsm + buf * BBUF;
#pragma unroll
        for (int p = 0; p < 4; p++) {
            float4 v = ra[p];
            v.x = to_tf32(v.x); v.y = to_tf32(v.y); v.z = to_tf32(v.z); v.w = to_tf32(v.w);
            *(float4*)(a + (p * 32 + rr) * ASTRIDE + c4 * 4) = v;
        }
#pragma unroll
        for (int p = 0; p < 8; p++) {
            float4 v = rb[p];
            v.x = to_tf32(v.x); v.y = to_tf32(v.y); v.z = to_tf32(v.z); v.w = to_tf32(v.w);
            *(float4*)(b + (p * 32 + rr) * ASTRIDE + c4 * 4) = v;
        }
    };
    auto compute = [&](int buf) {
        const float* a = Asm + buf * ABUF;
        const float* b = Bsm + buf * BBUF;
        int r = lane >> 2, c = lane & 3;
#pragma unroll
        for (int kk = 0; kk < 4; kk++) {
            uint32_t af[4][4], bf[8][2];
#pragma unroll
            for (int im = 0; im < 4; im++) {
                const float* ap = a + (wm + im * 16 + r) * ASTRIDE + kk * 8 + c;
                af[im][0] = __float_as_uint(ap[0]);
                af[im][1] = __float_as_uint(ap[8 * ASTRIDE]);
                af[im][2] = __float_as_uint(ap[4]);
                af[im][3] = __float_as_uint(ap[8 * ASTRIDE + 4]);
            }
#pragma unroll
            for (int jn = 0; jn < 8; jn++) {
                const float* bp = b + (wn + jn * 8 + r) * ASTRIDE + kk * 8 + c;
                bf[jn][0] = __float_as_uint(bp[0]);
                bf[jn][1] = __float_as_uint(bp[4]);
            }
#pragma unroll
            for (int im = 0; im < 4; im++)
#pragma unroll
                for (int jn = 0; jn < 8; jn++)
                    mma_tf32(acc[im][jn], af[im], bf[jn]);
        }
    };

    issue_load(0);
    store_smem(0);
    __syncthreads();
    for (int kc = 0; kc < nch; kc++) {
        if (kc + 1 < nch) issue_load(kc + 1);
        compute(kc & 1);
        if (kc + 1 < nch) {
            __syncthreads();
            store_smem((kc + 1) & 1);
        }
        __syncthreads();
    }

    // epilogue: c0,c1 at (row, 2c..2c+1); c2,c3 at (row+8, ...)
    int r = lane >> 2, c2 = (lane & 3) * 2;
#pragma unroll
    for (int im = 0; im < 4; im++) {
#pragma unroll
        for (int jn = 0; jn < 8; jn++) {
            int row = row0 + wm + im * 16 + r;
            int col = wn + jn * 8 + c2;
            float2 v0 = make_float2(acc[im][jn][0], acc[im][jn][1]);
            float2 v1 = make_float2(acc[im][jn][2], acc[im][jn][3]);
            *(float2*)(C + (size_t)row * 256 + col) = v0;
            *(float2*)(C + (size_t)(row + 8) * 256 + col) = v1;
        }
    }
}

// ---------------- non-GEMM kernels -------------------------------------------
__global__ void segmean_kernel(const float* __restrict__ x, const int* __restrict__ dom) {
    __shared__ int s_lo, s_hi;
    int d = blockIdx.x;
    if (threadIdx.x == 0) {
        s_lo = lower_bound_dev(dom, N_ATOMS, d);
        s_hi = lower_bound_dev(dom, N_ATOMS, d + 1);
    }
    __syncthreads();
    int lo = s_lo, hi = s_hi, c = threadIdx.x;
    float s = 0.f;
    for (int r = lo; r < hi; r++) s += x[(size_t)r * CH + c];
    int cnt = hi - lo;
    g_xinv[(size_t)d * CH + c] = s / (float)(cnt > 0 ? cnt : 1);
}

__global__ void segmsg_kernel(const float* __restrict__ x, const int* __restrict__ ii,
                              const int* __restrict__ src) {
    __shared__ int s_lo, s_hi;
    int m = blockIdx.x;
    if (threadIdx.x == 0) {
        s_lo = lower_bound_dev(ii, E_EDGE, m);
        s_hi = lower_bound_dev(ii, E_EDGE, m + 1);
    }
    __syncthreads();
    int lo = s_lo, hi = s_hi, c = threadIdx.x;
    float s = 0.f;
    for (int e = lo; e < hi; e++) s += x[(size_t)src[e] * CH + c];
    g_msg[(size_t)m * CH + c] = s;
}

__global__ void dom_scatter_kernel(const int* __restrict__ dme) {
    int m = blockIdx.x * 4 + (threadIdx.x >> 6);
    int c = threadIdx.x & 63;
    int d0 = dme[m];
    int d1 = dme[M_MSG + m];
    float4 a = ((const float4*)g_msg)[(size_t)m * 64 + c];
    float4 b = ((const float4*)g_xinv)[(size_t)d0 * 64 + c];
    red_add_v4(&g_r1[((size_t)d1 * 64 + c) * 4], a);
    red_add_v4(&g_r2[((size_t)d1 * 64 + c) * 4], b);
}

__global__ void edge_scatter_kernel(const int* __restrict__ nme, const int* __restrict__ ii,
                                    const int* __restrict__ dme, float* __restrict__ out) {
    int e = blockIdx.x * 4 + (threadIdx.x >> 6);
    int c = threadIdx.x & 63;
    int s = nme[e];
    int t = nme[E_EDGE + e];
    int m = ii[e];
    int d0 = dme[m];
    float4 a = ((const float4*)g_xa)[(size_t)s * 64 + c];
    float4 b = ((const float4*)g_msgb)[(size_t)m * 64 + c];
    float4 u = ((const float4*)g_u2)[(size_t)d0 * 64 + c];
    float4 v = make_float4(a.x + b.x + u.x, a.y + b.y + u.y, a.z + b.z + u.z, a.w + b.w + u.w);
    red_add_v4(out + (size_t)t * 256 + c * 4, v);
}

__global__ void final_add_kernel(const int* __restrict__ dom, float* __restrict__ out) {
    int n = blockIdx.x * 4 + (threadIdx.x >> 6);
    int c = threadIdx.x & 63;
    int d = dom[n];
    float4 v = ((float4*)out)[(size_t)n * 64 + c];
    float4 i1 = ((const float4*)g_inv)[(size_t)d * 64 + c];
    float4 i2 = ((const float4*)g_inv2)[(size_t)d * 64 + c];
    v.x += i1.x + i2.x; v.y += i1.y + i2.y; v.z += i1.z + i2.z; v.w += i1.w + i2.w;
    ((float4*)out)[(size_t)n * 64 + c] = v;
}

// ---------------- launch ------------------------------------------------------
extern "C" void kernel_launch(void* const* d_in, const int* in_sizes, int n_in,
                              void* d_out, int out_size) {
    const float* x        = (const float*)d_in[0];
    const int*   dom      = (const int*)d_in[1];
    const int*   nme      = (const int*)d_in[2];   // [2, E] : src then tgt
    const int*   ii       = (const int*)d_in[3];
    const int*   dme      = (const int*)d_in[4];   // [2, M] : dme0 then dme1
    const float* Wtf_int  = (const float*)d_in[5]; // [256, 768]
    const float* Wtf_inv  = (const float*)d_in[6]; // [256, 512]
    const float* Wlin_inv = (const float*)d_in[7]; // [256, 256]
    const float* Wlin_id  = (const float*)d_in[8]; // [256, 256]
    float* out = (float*)d_out;

    float *xa, *msg, *msgb, *xinv, *u2, *r1, *r2, *inv, *inv2;
    cudaGetSymbolAddress((void**)&xa,   g_xa);
    cudaGetSymbolAddress((void**)&msg,  g_msg);
    cudaGetSymbolAddress((void**)&msgb, g_msgb);
    cudaGetSymbolAddress((void**)&xinv, g_xinv);
    cudaGetSymbolAddress((void**)&u2,   g_u2);
    cudaGetSymbolAddress((void**)&r1,   g_r1);
    cudaGetSymbolAddress((void**)&r2,   g_r2);
    cudaGetSymbolAddress((void**)&inv,  g_inv);
    cudaGetSymbolAddress((void**)&inv2, g_inv2);

    // idempotent; no static guards allowed by the harness rules
    cudaFuncSetAttribute(mma_gemm, cudaFuncAttributeMaxDynamicSharedMemorySize, SMEMSZ);

    // segment reductions (sorted indicators -> binary-searched ranges)
    segmean_kernel<<<D_DOM, 256>>>(x, dom);
    segmsg_kernel<<<M_MSG, 256>>>(x, ii, nme);

    // r1 = segsum(msg, dme1); r2 = segsum(x_inv[dme0], dme1)
    cudaMemsetAsync(r1, 0, (size_t)D_DOM * CH * sizeof(float), 0);
    cudaMemsetAsync(r2, 0, (size_t)D_DOM * CH * sizeof(float), 0);
    dom_scatter_kernel<<<M_MSG / 4, 256>>>(dme);

    // tf32 tensor-core GEMMs (mma.sync; compiles on plain sm_103 target)
    mma_gemm<<<N_ATOMS / 128, 256, SMEMSZ>>>(x,    Wlin_id,       256, nullptr, nullptr, 0, out);
    mma_gemm<<<N_ATOMS / 128, 256, SMEMSZ>>>(x,    Wtf_int,       768, nullptr, nullptr, 0, xa);
    mma_gemm<<<M_MSG  / 128, 256, SMEMSZ>>>(msg,  Wtf_int + 256, 768, nullptr, nullptr, 0, msgb);
    mma_gemm<<<D_DOM  / 128, 256, SMEMSZ>>>(xinv, Wlin_inv,      256, nullptr, nullptr, 0, inv);
    mma_gemm<<<D_DOM  / 128, 256, SMEMSZ>>>(xinv, Wtf_int + 512, 768, nullptr, nullptr, 0, u2);
    mma_gemm<<<D_DOM  / 128, 256, SMEMSZ>>>(r1,   Wtf_inv,       512, r2, Wtf_inv + 256, 512, inv2);

    // per-edge scatter of all three irreducible maps
    edge_scatter_kernel<<<E_EDGE / 4, 256>>>(nme, ii, dme, out);

    // add gathered invariant maps
    final_add_kernel<<<N_ATOMS / 4, 256>>>(dom, out);
}